// round 6
// baseline (speedup 1.0000x reference)
#include <cuda_runtime.h>
#include <cuda_bf16.h>
#include <cstdint>

#define BATCH 512
#define NNEG  2048
#define EDIM  256
#define KE    1536          // 3 * 512 (hi*hi | hi*lo | lo*hi)
#define KC    64            // bf16 K per chunk (128B row)
#define NCH   (KE / KC)     // 24 chunks

// Scratch: bf16 split operands, row-major K-contiguous.
__device__ __align__(16) __nv_bfloat16 g_Abf[BATCH * KE];
__device__ __align__(16) __nv_bfloat16 g_Bbf[NNEG  * KE];
__device__ float g_c[BATCH];

__device__ __forceinline__ uint32_t s2u(const void* p) {
    uint32_t a;
    asm("{ .reg .u64 t; cvta.to.shared.u64 t, %1; cvt.u32.u64 %0, t; }" : "=r"(a) : "l"(p));
    return a;
}
__device__ __forceinline__ uint32_t sw128(uint32_t off) {
    return off ^ ((off >> 3) & 0x70);
}

// ---------------------------------------------------------------------------
// Fused prep (unchanged — known good)
// ---------------------------------------------------------------------------
__device__ __forceinline__ void bsplit(float v, __nv_bfloat16& hi, __nv_bfloat16& lo) {
    hi = __float2bfloat16(v);
    lo = __float2bfloat16(v - __bfloat162float(hi));
}

__global__ void prep_kernel(const float* __restrict__ head,
                            const float* __restrict__ tail,
                            const float* __restrict__ rel,
                            const int* __restrict__ rid) {
    int blk = blockIdx.x;
    int e = threadIdx.x;           // 0..255
    __shared__ float red[8];

    if (blk < BATCH) {
        int b = blk;
        float h = head[b * EDIM + e];
        float v = h * h;
        #pragma unroll
        for (int o = 16; o > 0; o >>= 1) v += __shfl_xor_sync(0xffffffffu, v, o);
        if ((e & 31) == 0) red[e >> 5] = v;
        __syncthreads();
        float s = 0.f;
        #pragma unroll
        for (int i = 0; i < 8; i++) s += red[i];
        float hn = h / fmaxf(sqrtf(s), 1e-12f);

        int r = rid[b];
        const float* rrow = rel + (size_t)r * (2 * EDIM);
        float rh = rrow[e];
        float rt = rrow[EDIM + e];
        float hh = hn * rh;

        float v1 = rt * rt;
        float v2 = -2.f * rt * hh;
        __nv_bfloat16 h1, l1, h2, l2;
        bsplit(v1, h1, l1);
        bsplit(v2, h2, l2);
        size_t ra = (size_t)b * KE;
        g_Abf[ra + e]               = h1;   // seg0: hi   (x B hi)
        g_Abf[ra + EDIM + e]        = h2;
        g_Abf[ra + 512 + e]         = h1;   // seg1: hi   (x B lo)
        g_Abf[ra + 512 + EDIM + e]  = h2;
        g_Abf[ra + 1024 + e]        = l1;   // seg2: lo   (x B hi)
        g_Abf[ra + 1024 + EDIM + e] = l2;

        __syncthreads();
        v = hh * hh;
        #pragma unroll
        for (int o = 16; o > 0; o >>= 1) v += __shfl_xor_sync(0xffffffffu, v, o);
        if ((e & 31) == 0) red[e >> 5] = v;
        __syncthreads();
        if (e == 0) {
            float c = 0.f;
            #pragma unroll
            for (int i = 0; i < 8; i++) c += red[i];
            g_c[b] = c;
        }
    } else {
        int j = blk - BATCH;
        float t = tail[j * EDIM + e];
        float v = t * t;
        #pragma unroll
        for (int o = 16; o > 0; o >>= 1) v += __shfl_xor_sync(0xffffffffu, v, o);
        if ((e & 31) == 0) red[e >> 5] = v;
        __syncthreads();
        float s = 0.f;
        #pragma unroll
        for (int i = 0; i < 8; i++) s += red[i];
        float tn = t / fmaxf(sqrtf(s), 1e-12f);

        float w1 = tn * tn;
        float w2 = tn;
        __nv_bfloat16 h1, l1, h2, l2;
        bsplit(w1, h1, l1);
        bsplit(w2, h2, l2);
        size_t rb = (size_t)j * KE;
        g_Bbf[rb + e]               = h1;   // seg0: hi
        g_Bbf[rb + EDIM + e]        = h2;
        g_Bbf[rb + 512 + e]         = l1;   // seg1: lo
        g_Bbf[rb + 512 + EDIM + e]  = l2;
        g_Bbf[rb + 1024 + e]        = h1;   // seg2: hi
        g_Bbf[rb + 1024 + EDIM + e] = h2;
    }
}

// ---------------------------------------------------------------------------
// HMMA GEMM: 64x64 tile, 256 CTAs (single resident wave @ occ>=2),
// 8 warps, warp tile 16x32, K=1536 in 24 chunks of 64.
// ---------------------------------------------------------------------------
#define BM 64
#define BN 64

__global__ void __launch_bounds__(256, 2)
gemm_mma_kernel(float* __restrict__ out) {
    __shared__ __align__(128) __nv_bfloat16 As[2][BM * KC];   // 8KB each
    __shared__ __align__(128) __nv_bfloat16 Bs[2][BN * KC];   // 8KB each

    int tid = threadIdx.x;             // 0..255
    int lane = tid & 31;
    int wid = tid >> 5;                // 0..7
    int wm = wid & 3;                  // 4 m-warps -> 16 rows each
    int wn = wid >> 2;                 // 2 n-warps -> 32 cols each
    int bn0 = blockIdx.x * BN;         // 32
    int bm0 = blockIdx.y * BM;         // 8

    int groupID = lane >> 2;           // 0..7
    int tig = lane & 3;                // 0..3

    float acc[4][4];
    #pragma unroll
    for (int ni = 0; ni < 4; ni++)
        #pragma unroll
        for (int q = 0; q < 4; q++) acc[ni][q] = 0.f;

    uint32_t asw = s2u(&As[0][0]);
    uint32_t bsw = s2u(&Bs[0][0]);

    // A x4 lane addressing: row = lane%8 + ((lane>>3)&1)*8, khalf = (lane>>4)*8
    int aRow = (lane & 7) + ((lane >> 3) & 1) * 8;
    int aKh  = (lane >> 4) * 8;
    // B x4 lane addressing (2 n-frags per ldmatrix):
    // group g = lane>>3: mat g -> n_off=(g>>1)*8, k_off=(g&1)*8
    int bRowOff = ((lane >> 4) & 1) * 8 + (lane & 7);   // n offset within 16
    int bKh     = ((lane >> 3) & 1) * 8;

    // LDG staging: A 2x uint4, B 2x uint4 per thread
    uint4 aReg[2], bReg[2];
    auto ldg_chunk = [&](int k0) {
        #pragma unroll
        for (int i = 0; i < 2; i++) {
            int idx = i * 256 + tid;           // 0..511
            int r = idx >> 3, c = idx & 7;     // r:0..63
            aReg[i] = *reinterpret_cast<const uint4*>(
                &g_Abf[(size_t)(bm0 + r) * KE + k0 + c * 8]);
            bReg[i] = *reinterpret_cast<const uint4*>(
                &g_Bbf[(size_t)(bn0 + r) * KE + k0 + c * 8]);
        }
    };
    auto sts_chunk = [&](int sel) {
        char* aB = reinterpret_cast<char*>(&As[sel][0]);
        char* bB = reinterpret_cast<char*>(&Bs[sel][0]);
        #pragma unroll
        for (int i = 0; i < 2; i++) {
            int idx = i * 256 + tid;
            int r = idx >> 3, c = idx & 7;
            uint32_t off = sw128(r * 128 + c * 16);
            *reinterpret_cast<uint4*>(aB + off) = aReg[i];
            *reinterpret_cast<uint4*>(bB + off) = bReg[i];
        }
    };

    ldg_chunk(0);
    sts_chunk(0);
    __syncthreads();

    for (int it = 0; it < NCH; it++) {
        int sel = it & 1;
        if (it + 1 < NCH) ldg_chunk((it + 1) * KC);

        uint32_t aBase = asw + sel * (BM * KC * 2);
        uint32_t bBase = bsw + sel * (BN * KC * 2);

        #pragma unroll
        for (int kk = 0; kk < 4; kk++) {       // 4 k-steps of 16
            // A fragment: 1 m16-tile
            uint32_t af[4];
            {
                int row = wm * 16 + aRow;
                int kcol = kk * 16 + aKh;
                uint32_t addr = aBase + sw128((uint32_t)(row * 128 + kcol * 2));
                asm volatile(
                    "ldmatrix.sync.aligned.m8n8.x4.shared.b16 {%0,%1,%2,%3}, [%4];"
                    : "=r"(af[0]), "=r"(af[1]), "=r"(af[2]), "=r"(af[3])
                    : "r"(addr));
            }
            // B fragments: 4 n8-tiles via 2 x ldmatrix.x4
            uint32_t bf[4][2];
            #pragma unroll
            for (int p = 0; p < 2; p++) {      // n-frag pairs {0,1}, {2,3}
                int n = wn * 32 + p * 16 + bRowOff;
                int kcol = kk * 16 + bKh;
                uint32_t addr = bBase + sw128((uint32_t)(n * 128 + kcol * 2));
                asm volatile(
                    "ldmatrix.sync.aligned.m8n8.x4.shared.b16 {%0,%1,%2,%3}, [%4];"
                    : "=r"(bf[p * 2][0]), "=r"(bf[p * 2][1]),
                      "=r"(bf[p * 2 + 1][0]), "=r"(bf[p * 2 + 1][1])
                    : "r"(addr));
            }
            #pragma unroll
            for (int ni = 0; ni < 4; ni++) {
                asm volatile(
                    "mma.sync.aligned.m16n8k16.row.col.f32.bf16.bf16.f32 "
                    "{%0,%1,%2,%3}, {%4,%5,%6,%7}, {%8,%9}, {%0,%1,%2,%3};"
                    : "+f"(acc[ni][0]), "+f"(acc[ni][1]),
                      "+f"(acc[ni][2]), "+f"(acc[ni][3])
                    : "r"(af[0]), "r"(af[1]), "r"(af[2]), "r"(af[3]),
                      "r"(bf[ni][0]), "r"(bf[ni][1]));
            }
        }
        __syncthreads();
        if (it + 1 < NCH) {
            sts_chunk(sel ^ 1);
            __syncthreads();
        }
    }

    // epilogue: rows bm0 + wm*16 + {groupID, groupID+8},
    // cols bn0 + wn*32 + ni*8 + tig*2. Add c[row], -sqrt, float2 stores.
    int r0 = bm0 + wm * 16 + groupID;
    int r1 = r0 + 8;
    float c0 = g_c[r0];
    float c1 = g_c[r1];
    #pragma unroll
    for (int ni = 0; ni < 4; ni++) {
        int col = bn0 + wn * 32 + ni * 8 + tig * 2;
        float2 v0, v1;
        v0.x = -sqrtf(fmaxf(acc[ni][0] + c0, 0.f));
        v0.y = -sqrtf(fmaxf(acc[ni][1] + c0, 0.f));
        v1.x = -sqrtf(fmaxf(acc[ni][2] + c1, 0.f));
        v1.y = -sqrtf(fmaxf(acc[ni][3] + c1, 0.f));
        *reinterpret_cast<float2*>(out + (size_t)r0 * NNEG + col) = v0;
        *reinterpret_cast<float2*>(out + (size_t)r1 * NNEG + col) = v1;
    }
}

// ---------------------------------------------------------------------------
extern "C" void kernel_launch(void* const* d_in, const int* in_sizes, int n_in,
                              void* d_out, int out_size) {
    const float* head = (const float*)d_in[0];       // (512, 256)
    const float* tail = (const float*)d_in[1];       // (1, 2048, 256)
    const float* rel  = (const float*)d_in[2];       // (1000, 512)
    const int*   rid  = (const int*)d_in[3];         // (512,) int32
    float* out = (float*)d_out;                      // (512, 2048)

    prep_kernel<<<BATCH + NNEG, EDIM>>>(head, tail, rel, rid);
    dim3 grid(NNEG / BN, BATCH / BM);
    gemm_mma_kernel<<<grid, 256>>>(out);
}

// round 7
// speedup vs baseline: 1.6330x; 1.6330x over previous
#include <cuda_runtime.h>
#include <cuda_fp16.h>
#include <cstdint>

#define BATCH 512
#define NNEG  2048
#define EDIM  256
#define KA    1024          // A: [hi | lo] fp16
#define KB    512           // B: [hi] fp16, read twice
#define KC    64            // fp16 K per chunk (128B row)
#define NCH   (KA / KC)     // 16 chunks
#define STG   3             // pipeline stages (48KB static smem)

// Scratch
__device__ __align__(16) __half g_Ah[BATCH * KA];
__device__ __align__(16) __half g_Bh[NNEG  * KB];
__device__ float g_c[BATCH];

__device__ __forceinline__ uint32_t s2u(const void* p) {
    uint32_t a;
    asm("{ .reg .u64 t; cvta.to.shared.u64 t, %1; cvt.u32.u64 %0, t; }" : "=r"(a) : "l"(p));
    return a;
}
__device__ __forceinline__ uint32_t sw128(uint32_t off) {
    return off ^ ((off >> 3) & 0x70);
}
__device__ __forceinline__ void cpasync16(uint32_t dst, const void* src) {
    asm volatile("cp.async.cg.shared.global [%0], [%1], 16;" :: "r"(dst), "l"(src));
}

// ---------------------------------------------------------------------------
// Fused prep: fp16 hi/lo split. A rows: [hi(v1)|hi(v2)|lo(v1)|lo(v2)] (K=1024),
// B rows: [hi(w1)|hi(w2)] (K=512).
// ---------------------------------------------------------------------------
__device__ __forceinline__ void hsplit(float v, __half& hi, __half& lo) {
    hi = __float2half(v);
    lo = __float2half(v - __half2float(hi));
}

__global__ void prep_kernel(const float* __restrict__ head,
                            const float* __restrict__ tail,
                            const float* __restrict__ rel,
                            const int* __restrict__ rid) {
    int blk = blockIdx.x;
    int e = threadIdx.x;           // 0..255
    __shared__ float red[8];

    if (blk < BATCH) {
        int b = blk;
        float h = head[b * EDIM + e];
        float v = h * h;
        #pragma unroll
        for (int o = 16; o > 0; o >>= 1) v += __shfl_xor_sync(0xffffffffu, v, o);
        if ((e & 31) == 0) red[e >> 5] = v;
        __syncthreads();
        float s = 0.f;
        #pragma unroll
        for (int i = 0; i < 8; i++) s += red[i];
        float hn = h / fmaxf(sqrtf(s), 1e-12f);

        int r = rid[b];
        const float* rrow = rel + (size_t)r * (2 * EDIM);
        float rh = rrow[e];
        float rt = rrow[EDIM + e];
        float hh = hn * rh;

        float v1 = rt * rt;
        float v2 = -2.f * rt * hh;
        __half h1, l1, h2, l2;
        hsplit(v1, h1, l1);
        hsplit(v2, h2, l2);
        size_t ra = (size_t)b * KA;
        g_Ah[ra + e]        = h1;
        g_Ah[ra + 256 + e]  = h2;
        g_Ah[ra + 512 + e]  = l1;
        g_Ah[ra + 768 + e]  = l2;

        __syncthreads();
        v = hh * hh;
        #pragma unroll
        for (int o = 16; o > 0; o >>= 1) v += __shfl_xor_sync(0xffffffffu, v, o);
        if ((e & 31) == 0) red[e >> 5] = v;
        __syncthreads();
        if (e == 0) {
            float c = 0.f;
            #pragma unroll
            for (int i = 0; i < 8; i++) c += red[i];
            g_c[b] = c;
        }
    } else {
        int j = blk - BATCH;
        float t = tail[j * EDIM + e];
        float v = t * t;
        #pragma unroll
        for (int o = 16; o > 0; o >>= 1) v += __shfl_xor_sync(0xffffffffu, v, o);
        if ((e & 31) == 0) red[e >> 5] = v;
        __syncthreads();
        float s = 0.f;
        #pragma unroll
        for (int i = 0; i < 8; i++) s += red[i];
        float tn = t / fmaxf(sqrtf(s), 1e-12f);

        size_t rb = (size_t)j * KB;
        g_Bh[rb + e]       = __float2half(tn * tn);
        g_Bh[rb + 256 + e] = __float2half(tn);
    }
}

// ---------------------------------------------------------------------------
// HMMA GEMM: 64x64 tile, 256 CTAs, 4 warps (warp tile 32x32),
// fp16 K=1024 in 16 chunks, cp.async 3-stage, one sync per chunk.
// ---------------------------------------------------------------------------
#define BM 64
#define BN 64

__global__ void __launch_bounds__(128, 3)
gemm_mma_kernel(float* __restrict__ out) {
    __shared__ __align__(128) __half As[STG][BM * KC];   // 8KB/stage
    __shared__ __align__(128) __half Bs[STG][BN * KC];   // 8KB/stage

    int tid = threadIdx.x;             // 0..127
    int lane = tid & 31;
    int wid = tid >> 5;                // 0..3
    int wm = wid & 1;                  // 2 m-warps -> 32 rows
    int wn = wid >> 1;                 // 2 n-warps -> 32 cols
    int bn0 = blockIdx.x * BN;         // 32
    int bm0 = blockIdx.y * BM;         // 8

    int groupID = lane >> 2;
    int tig = lane & 3;

    float acc[2][4][4];
    #pragma unroll
    for (int mi = 0; mi < 2; mi++)
        #pragma unroll
        for (int ni = 0; ni < 4; ni++)
            #pragma unroll
            for (int q = 0; q < 4; q++) acc[mi][ni][q] = 0.f;

    uint32_t asw = s2u(&As[0][0]);
    uint32_t bsw = s2u(&Bs[0][0]);

    // verified ldmatrix lane addressing (R5/R6)
    int aRow = (lane & 7) + ((lane >> 3) & 1) * 8;
    int aKh  = (lane >> 4) * 8;
    int bRowOff = ((lane >> 4) & 1) * 8 + (lane & 7);
    int bKh     = ((lane >> 3) & 1) * 8;

    // issue chunk ic into stage ic%STG (8 cp.async of 16B per thread)
    auto issue = [&](int ic) {
        if (ic < NCH) {
            int stg = ic % STG;
            uint32_t aD = asw + stg * (BM * KC * 2);
            uint32_t bD = bsw + stg * (BN * KC * 2);
            int ka = ic * KC;
            int kb = (ic * KC) & (KB - 1);
            #pragma unroll
            for (int i = 0; i < 4; i++) {
                int idx = i * 128 + tid;           // 0..511
                int r = idx >> 3, c = idx & 7;     // r:0..63
                cpasync16(aD + sw128(r * 128 + c * 16),
                          &g_Ah[(size_t)(bm0 + r) * KA + ka + c * 8]);
                cpasync16(bD + sw128(r * 128 + c * 16),
                          &g_Bh[(size_t)(bn0 + r) * KB + kb + c * 8]);
            }
        }
        asm volatile("cp.async.commit_group;" ::: "memory");
    };

    issue(0);
    issue(1);

    for (int it = 0; it < NCH; it++) {
        asm volatile("cp.async.wait_group 1;" ::: "memory");
        __syncthreads();
        issue(it + 2);

        int stg = it % STG;
        uint32_t aBase = asw + stg * (BM * KC * 2);
        uint32_t bBase = bsw + stg * (BN * KC * 2);

        #pragma unroll
        for (int kk = 0; kk < 4; kk++) {       // 4 k-steps of 16
            uint32_t af[2][4];
            #pragma unroll
            for (int mi = 0; mi < 2; mi++) {
                int row = wm * 32 + mi * 16 + aRow;
                int kcol = kk * 16 + aKh;
                uint32_t addr = aBase + sw128((uint32_t)(row * 128 + kcol * 2));
                asm volatile(
                    "ldmatrix.sync.aligned.m8n8.x4.shared.b16 {%0,%1,%2,%3}, [%4];"
                    : "=r"(af[mi][0]), "=r"(af[mi][1]), "=r"(af[mi][2]), "=r"(af[mi][3])
                    : "r"(addr));
            }
            uint32_t bf[4][2];
            #pragma unroll
            for (int p = 0; p < 2; p++) {
                int n = wn * 32 + p * 16 + bRowOff;
                int kcol = kk * 16 + bKh;
                uint32_t addr = bBase + sw128((uint32_t)(n * 128 + kcol * 2));
                asm volatile(
                    "ldmatrix.sync.aligned.m8n8.x4.shared.b16 {%0,%1,%2,%3}, [%4];"
                    : "=r"(bf[p * 2][0]), "=r"(bf[p * 2][1]),
                      "=r"(bf[p * 2 + 1][0]), "=r"(bf[p * 2 + 1][1])
                    : "r"(addr));
            }
            #pragma unroll
            for (int mi = 0; mi < 2; mi++)
                #pragma unroll
                for (int ni = 0; ni < 4; ni++) {
                    asm volatile(
                        "mma.sync.aligned.m16n8k16.row.col.f32.f16.f16.f32 "
                        "{%0,%1,%2,%3}, {%4,%5,%6,%7}, {%8,%9}, {%0,%1,%2,%3};"
                        : "+f"(acc[mi][ni][0]), "+f"(acc[mi][ni][1]),
                          "+f"(acc[mi][ni][2]), "+f"(acc[mi][ni][3])
                        : "r"(af[mi][0]), "r"(af[mi][1]), "r"(af[mi][2]), "r"(af[mi][3]),
                          "r"(bf[ni][0]), "r"(bf[ni][1]));
                }
        }
    }

    // epilogue
    #pragma unroll
    for (int mi = 0; mi < 2; mi++) {
        int r0 = bm0 + wm * 32 + mi * 16 + groupID;
        int r1 = r0 + 8;
        float c0 = g_c[r0];
        float c1 = g_c[r1];
        #pragma unroll
        for (int ni = 0; ni < 4; ni++) {
            int col = bn0 + wn * 32 + ni * 8 + tig * 2;
            float2 v0, v1;
            v0.x = -sqrtf(fmaxf(acc[mi][ni][0] + c0, 0.f));
            v0.y = -sqrtf(fmaxf(acc[mi][ni][1] + c0, 0.f));
            v1.x = -sqrtf(fmaxf(acc[mi][ni][2] + c1, 0.f));
            v1.y = -sqrtf(fmaxf(acc[mi][ni][3] + c1, 0.f));
            *reinterpret_cast<float2*>(out + (size_t)r0 * NNEG + col) = v0;
            *reinterpret_cast<float2*>(out + (size_t)r1 * NNEG + col) = v1;
        }
    }
}

// ---------------------------------------------------------------------------
extern "C" void kernel_launch(void* const* d_in, const int* in_sizes, int n_in,
                              void* d_out, int out_size) {
    const float* head = (const float*)d_in[0];       // (512, 256)
    const float* tail = (const float*)d_in[1];       // (1, 2048, 256)
    const float* rel  = (const float*)d_in[2];       // (1000, 512)
    const int*   rid  = (const int*)d_in[3];         // (512,) int32
    float* out = (float*)d_out;                      // (512, 2048)

    prep_kernel<<<BATCH + NNEG, EDIM>>>(head, tail, rel, rid);
    dim3 grid(NNEG / BN, BATCH / BM);
    gemm_mma_kernel<<<grid, 128>>>(out);
}

// round 8
// speedup vs baseline: 2.1425x; 1.3120x over previous
#include <cuda_runtime.h>
#include <cuda_fp16.h>
#include <cstdint>

#define BATCH 512
#define NNEG  2048
#define EDIM  256
#define KDIM  512           // pure fp16: K = 2*E
#define KC    64            // fp16 K per chunk (128B row)
#define NCH   (KDIM / KC)   // 8 chunks
#define STG   3

// Scratch
__device__ __align__(16) __half g_Ah[BATCH * KDIM];
__device__ __align__(16) __half g_Bh[NNEG  * KDIM];
__device__ float g_c[BATCH];

__device__ __forceinline__ uint32_t s2u(const void* p) {
    uint32_t a;
    asm("{ .reg .u64 t; cvta.to.shared.u64 t, %1; cvt.u32.u64 %0, t; }" : "=r"(a) : "l"(p));
    return a;
}
__device__ __forceinline__ uint32_t sw128(uint32_t off) {
    return off ^ ((off >> 3) & 0x70);
}
__device__ __forceinline__ void cpasync16(uint32_t dst, const void* src) {
    asm volatile("cp.async.cg.shared.global [%0], [%1], 16;" :: "r"(dst), "l"(src));
}
__device__ __forceinline__ float wredsum(float v) {
    #pragma unroll
    for (int o = 16; o > 0; o >>= 1) v += __shfl_xor_sync(0xffffffffu, v, o);
    return v;
}
// pack 8 floats -> 8 fp16 in a uint4
__device__ __forceinline__ uint4 pack8(const float* v) {
    union { uint4 u; __half2 h[4]; } r;
    r.h[0] = __floats2half2_rn(v[0], v[1]);
    r.h[1] = __floats2half2_rn(v[2], v[3]);
    r.h[2] = __floats2half2_rn(v[4], v[5]);
    r.h[3] = __floats2half2_rn(v[6], v[7]);
    return r.u;
}

// ---------------------------------------------------------------------------
// Warp-per-row prep: block = 8 warps = 8 rows; lane owns 8 elems.
// Rows [0,512) = A side (+c); rows [512,2560) = B side. No __syncthreads.
// ---------------------------------------------------------------------------
__global__ void __launch_bounds__(256)
prep_kernel(const float* __restrict__ head,
            const float* __restrict__ tail,
            const float* __restrict__ rel,
            const int* __restrict__ rid) {
    int lane = threadIdx.x & 31;
    int wid = threadIdx.x >> 5;
    int g = blockIdx.x * 8 + wid;
    int e0 = lane * 8;

    if (g < BATCH) {
        int b = g;
        float hv[8];
        *reinterpret_cast<float4*>(hv)     = *reinterpret_cast<const float4*>(&head[b * EDIM + e0]);
        *reinterpret_cast<float4*>(hv + 4) = *reinterpret_cast<const float4*>(&head[b * EDIM + e0 + 4]);
        float s = 0.f;
        #pragma unroll
        for (int i = 0; i < 8; i++) s += hv[i] * hv[i];
        s = wredsum(s);
        float inv = 1.f / fmaxf(sqrtf(s), 1e-12f);

        int r = rid[b];
        const float* rrow = rel + (size_t)r * KDIM;
        float rh[8], rt[8];
        *reinterpret_cast<float4*>(rh)     = *reinterpret_cast<const float4*>(&rrow[e0]);
        *reinterpret_cast<float4*>(rh + 4) = *reinterpret_cast<const float4*>(&rrow[e0 + 4]);
        *reinterpret_cast<float4*>(rt)     = *reinterpret_cast<const float4*>(&rrow[EDIM + e0]);
        *reinterpret_cast<float4*>(rt + 4) = *reinterpret_cast<const float4*>(&rrow[EDIM + e0 + 4]);

        float v1[8], v2[8], cs = 0.f;
        #pragma unroll
        for (int i = 0; i < 8; i++) {
            float hh = hv[i] * inv * rh[i];
            v1[i] = rt[i] * rt[i];
            v2[i] = -2.f * rt[i] * hh;
            cs += hh * hh;
        }
        size_t ra = (size_t)b * KDIM;
        *reinterpret_cast<uint4*>(&g_Ah[ra + e0])        = pack8(v1);
        *reinterpret_cast<uint4*>(&g_Ah[ra + EDIM + e0]) = pack8(v2);
        cs = wredsum(cs);
        if (lane == 0) g_c[b] = cs;
    } else {
        int j = g - BATCH;
        float tv[8];
        *reinterpret_cast<float4*>(tv)     = *reinterpret_cast<const float4*>(&tail[j * EDIM + e0]);
        *reinterpret_cast<float4*>(tv + 4) = *reinterpret_cast<const float4*>(&tail[j * EDIM + e0 + 4]);
        float s = 0.f;
        #pragma unroll
        for (int i = 0; i < 8; i++) s += tv[i] * tv[i];
        s = wredsum(s);
        float inv = 1.f / fmaxf(sqrtf(s), 1e-12f);

        float w1[8], w2[8];
        #pragma unroll
        for (int i = 0; i < 8; i++) {
            float tn = tv[i] * inv;
            w1[i] = tn * tn;
            w2[i] = tn;
        }
        size_t rb = (size_t)j * KDIM;
        *reinterpret_cast<uint4*>(&g_Bh[rb + e0])        = pack8(w1);
        *reinterpret_cast<uint4*>(&g_Bh[rb + EDIM + e0]) = pack8(w2);
    }
}

// ---------------------------------------------------------------------------
// HMMA GEMM: 64x64 tile, 256 CTAs, 4 warps (warp tile 32x32),
// fp16 K=512 in 8 chunks, cp.async 3-stage, one sync per chunk.
// ---------------------------------------------------------------------------
#define BM 64
#define BN 64

__global__ void __launch_bounds__(128, 3)
gemm_mma_kernel(float* __restrict__ out) {
    __shared__ __align__(128) __half As[STG][BM * KC];   // 8KB/stage
    __shared__ __align__(128) __half Bs[STG][BN * KC];   // 8KB/stage

    int tid = threadIdx.x;             // 0..127
    int lane = tid & 31;
    int wid = tid >> 5;                // 0..3
    int wm = wid & 1;                  // 2 m-warps -> 32 rows
    int wn = wid >> 1;                 // 2 n-warps -> 32 cols
    int bn0 = blockIdx.x * BN;         // 32
    int bm0 = blockIdx.y * BM;         // 8

    int groupID = lane >> 2;
    int tig = lane & 3;

    float acc[2][4][4];
    #pragma unroll
    for (int mi = 0; mi < 2; mi++)
        #pragma unroll
        for (int ni = 0; ni < 4; ni++)
            #pragma unroll
            for (int q = 0; q < 4; q++) acc[mi][ni][q] = 0.f;

    uint32_t asw = s2u(&As[0][0]);
    uint32_t bsw = s2u(&Bs[0][0]);

    // verified ldmatrix lane addressing (R5-R7)
    int aRow = (lane & 7) + ((lane >> 3) & 1) * 8;
    int aKh  = (lane >> 4) * 8;
    int bRowOff = ((lane >> 4) & 1) * 8 + (lane & 7);
    int bKh     = ((lane >> 3) & 1) * 8;

    auto issue = [&](int ic) {
        if (ic < NCH) {
            int stg = ic % STG;
            uint32_t aD = asw + stg * (BM * KC * 2);
            uint32_t bD = bsw + stg * (BN * KC * 2);
            int k0 = ic * KC;
            #pragma unroll
            for (int i = 0; i < 4; i++) {
                int idx = i * 128 + tid;           // 0..511
                int r = idx >> 3, c = idx & 7;     // r:0..63
                cpasync16(aD + sw128(r * 128 + c * 16),
                          &g_Ah[(size_t)(bm0 + r) * KDIM + k0 + c * 8]);
                cpasync16(bD + sw128(r * 128 + c * 16),
                          &g_Bh[(size_t)(bn0 + r) * KDIM + k0 + c * 8]);
            }
        }
        asm volatile("cp.async.commit_group;" ::: "memory");
    };

    issue(0);
    issue(1);

    for (int it = 0; it < NCH; it++) {
        asm volatile("cp.async.wait_group 1;" ::: "memory");
        __syncthreads();
        issue(it + 2);

        int stg = it % STG;
        uint32_t aBase = asw + stg * (BM * KC * 2);
        uint32_t bBase = bsw + stg * (BN * KC * 2);

        #pragma unroll
        for (int kk = 0; kk < 4; kk++) {       // 4 k-steps of 16
            uint32_t af[2][4];
            #pragma unroll
            for (int mi = 0; mi < 2; mi++) {
                int row = wm * 32 + mi * 16 + aRow;
                int kcol = kk * 16 + aKh;
                uint32_t addr = aBase + sw128((uint32_t)(row * 128 + kcol * 2));
                asm volatile(
                    "ldmatrix.sync.aligned.m8n8.x4.shared.b16 {%0,%1,%2,%3}, [%4];"
                    : "=r"(af[mi][0]), "=r"(af[mi][1]), "=r"(af[mi][2]), "=r"(af[mi][3])
                    : "r"(addr));
            }
            uint32_t bf[4][2];
            #pragma unroll
            for (int p = 0; p < 2; p++) {
                int n = wn * 32 + p * 16 + bRowOff;
                int kcol = kk * 16 + bKh;
                uint32_t addr = bBase + sw128((uint32_t)(n * 128 + kcol * 2));
                asm volatile(
                    "ldmatrix.sync.aligned.m8n8.x4.shared.b16 {%0,%1,%2,%3}, [%4];"
                    : "=r"(bf[p * 2][0]), "=r"(bf[p * 2][1]),
                      "=r"(bf[p * 2 + 1][0]), "=r"(bf[p * 2 + 1][1])
                    : "r"(addr));
            }
            #pragma unroll
            for (int mi = 0; mi < 2; mi++)
                #pragma unroll
                for (int ni = 0; ni < 4; ni++) {
                    asm volatile(
                        "mma.sync.aligned.m16n8k16.row.col.f32.f16.f16.f32 "
                        "{%0,%1,%2,%3}, {%4,%5,%6,%7}, {%8,%9}, {%0,%1,%2,%3};"
                        : "+f"(acc[mi][ni][0]), "+f"(acc[mi][ni][1]),
                          "+f"(acc[mi][ni][2]), "+f"(acc[mi][ni][3])
                        : "r"(af[mi][0]), "r"(af[mi][1]), "r"(af[mi][2]), "r"(af[mi][3]),
                          "r"(bf[ni][0]), "r"(bf[ni][1]));
                }
        }
    }

    // epilogue
    #pragma unroll
    for (int mi = 0; mi < 2; mi++) {
        int r0 = bm0 + wm * 32 + mi * 16 + groupID;
        int r1 = r0 + 8;
        float c0 = g_c[r0];
        float c1 = g_c[r1];
        #pragma unroll
        for (int ni = 0; ni < 4; ni++) {
            int col = bn0 + wn * 32 + ni * 8 + tig * 2;
            float2 v0, v1;
            v0.x = -sqrtf(fmaxf(acc[mi][ni][0] + c0, 0.f));
            v0.y = -sqrtf(fmaxf(acc[mi][ni][1] + c0, 0.f));
            v1.x = -sqrtf(fmaxf(acc[mi][ni][2] + c1, 0.f));
            v1.y = -sqrtf(fmaxf(acc[mi][ni][3] + c1, 0.f));
            *reinterpret_cast<float2*>(out + (size_t)r0 * NNEG + col) = v0;
            *reinterpret_cast<float2*>(out + (size_t)r1 * NNEG + col) = v1;
        }
    }
}

// ---------------------------------------------------------------------------
extern "C" void kernel_launch(void* const* d_in, const int* in_sizes, int n_in,
                              void* d_out, int out_size) {
    const float* head = (const float*)d_in[0];       // (512, 256)
    const float* tail = (const float*)d_in[1];       // (1, 2048, 256)
    const float* rel  = (const float*)d_in[2];       // (1000, 512)
    const int*   rid  = (const int*)d_in[3];         // (512,) int32
    float* out = (float*)d_out;                      // (512, 2048)

    prep_kernel<<<(BATCH + NNEG) / 8, 256>>>(head, tail, rel, rid);
    dim3 grid(NNEG / BN, BATCH / BM);
    gemm_mma_kernel<<<grid, 128>>>(out);
}

// round 9
// speedup vs baseline: 2.1855x; 1.0201x over previous
#include <cuda_runtime.h>
#include <cuda_fp16.h>
#include <cstdint>

#define BATCH 512
#define NNEG  2048
#define EDIM  256
#define KDIM  512           // pure fp16: K = 2*E
#define KC    64            // fp16 K per chunk (128B row)
#define NCH   (KDIM / KC)   // 8 chunks
#define STG   3
#define NCTA  256

// Scratch
__device__ __align__(16) __half g_Ah[BATCH * KDIM];
__device__ __align__(16) __half g_Bh[NNEG  * KDIM];
__device__ float g_c[BATCH];
__device__ unsigned long long g_bar;   // monotonic grid-barrier counter

__device__ __forceinline__ uint32_t s2u(const void* p) {
    uint32_t a;
    asm("{ .reg .u64 t; cvta.to.shared.u64 t, %1; cvt.u32.u64 %0, t; }" : "=r"(a) : "l"(p));
    return a;
}
__device__ __forceinline__ uint32_t sw128(uint32_t off) {
    return off ^ ((off >> 3) & 0x70);
}
__device__ __forceinline__ void cpasync16(uint32_t dst, const void* src) {
    asm volatile("cp.async.cg.shared.global [%0], [%1], 16;" :: "r"(dst), "l"(src));
}
__device__ __forceinline__ float wredsum(float v) {
    #pragma unroll
    for (int o = 16; o > 0; o >>= 1) v += __shfl_xor_sync(0xffffffffu, v, o);
    return v;
}
__device__ __forceinline__ uint4 pack8(const float* v) {
    union { uint4 u; __half2 h[4]; } r;
    r.h[0] = __floats2half2_rn(v[0], v[1]);
    r.h[1] = __floats2half2_rn(v[2], v[3]);
    r.h[2] = __floats2half2_rn(v[4], v[5]);
    r.h[3] = __floats2half2_rn(v[6], v[7]);
    return r.u;
}

// ---------------------------------------------------------------------------
// Prep one A row (normalize head, gather rel, write fp16 A' + c)
// ---------------------------------------------------------------------------
__device__ __forceinline__ void prep_a_row(int b, int lane,
                                           const float* __restrict__ head,
                                           const float* __restrict__ rel,
                                           const int* __restrict__ rid) {
    int e0 = lane * 8;
    float hv[8];
    *reinterpret_cast<float4*>(hv)     = *reinterpret_cast<const float4*>(&head[b * EDIM + e0]);
    *reinterpret_cast<float4*>(hv + 4) = *reinterpret_cast<const float4*>(&head[b * EDIM + e0 + 4]);
    float s = 0.f;
    #pragma unroll
    for (int i = 0; i < 8; i++) s += hv[i] * hv[i];
    s = wredsum(s);
    float inv = 1.f / fmaxf(sqrtf(s), 1e-12f);

    int r = rid[b];
    const float* rrow = rel + (size_t)r * KDIM;
    float rh[8], rt[8];
    *reinterpret_cast<float4*>(rh)     = *reinterpret_cast<const float4*>(&rrow[e0]);
    *reinterpret_cast<float4*>(rh + 4) = *reinterpret_cast<const float4*>(&rrow[e0 + 4]);
    *reinterpret_cast<float4*>(rt)     = *reinterpret_cast<const float4*>(&rrow[EDIM + e0]);
    *reinterpret_cast<float4*>(rt + 4) = *reinterpret_cast<const float4*>(&rrow[EDIM + e0 + 4]);

    float v1[8], v2[8], cs = 0.f;
    #pragma unroll
    for (int i = 0; i < 8; i++) {
        float hh = hv[i] * inv * rh[i];
        v1[i] = rt[i] * rt[i];
        v2[i] = -2.f * rt[i] * hh;
        cs += hh * hh;
    }
    size_t ra = (size_t)b * KDIM;
    *reinterpret_cast<uint4*>(&g_Ah[ra + e0])        = pack8(v1);
    *reinterpret_cast<uint4*>(&g_Ah[ra + EDIM + e0]) = pack8(v2);
    cs = wredsum(cs);
    if (lane == 0) g_c[b] = cs;
}

__device__ __forceinline__ void prep_b_row(int j, int lane,
                                           const float* __restrict__ tail) {
    int e0 = lane * 8;
    float tv[8];
    *reinterpret_cast<float4*>(tv)     = *reinterpret_cast<const float4*>(&tail[j * EDIM + e0]);
    *reinterpret_cast<float4*>(tv + 4) = *reinterpret_cast<const float4*>(&tail[j * EDIM + e0 + 4]);
    float s = 0.f;
    #pragma unroll
    for (int i = 0; i < 8; i++) s += tv[i] * tv[i];
    s = wredsum(s);
    float inv = 1.f / fmaxf(sqrtf(s), 1e-12f);

    float w1[8], w2[8];
    #pragma unroll
    for (int i = 0; i < 8; i++) {
        float tn = tv[i] * inv;
        w1[i] = tn * tn;
        w2[i] = tn;
    }
    size_t rb = (size_t)j * KDIM;
    *reinterpret_cast<uint4*>(&g_Bh[rb + e0])        = pack8(w1);
    *reinterpret_cast<uint4*>(&g_Bh[rb + EDIM + e0]) = pack8(w2);
}

// ---------------------------------------------------------------------------
// Fused kernel: prep slice -> grid barrier -> HMMA GEMM (R8 body).
// 64x64 tile, 256 CTAs, 4 warps, fp16 K=512, cp.async 3-stage.
// ---------------------------------------------------------------------------
#define BM 64
#define BN 64

__global__ void __launch_bounds__(128, 3)
fused_kernel(float* __restrict__ out,
             const float* __restrict__ head,
             const float* __restrict__ tail,
             const float* __restrict__ rel,
             const int* __restrict__ rid) {
    __shared__ __align__(128) __half As[STG][BM * KC];
    __shared__ __align__(128) __half Bs[STG][BN * KC];

    int tid = threadIdx.x;
    int lane = tid & 31;
    int wid = tid >> 5;                // 0..3
    int flat = blockIdx.y * 32 + blockIdx.x;   // 0..255

    // ---- Phase 1: prep. 10 row-tasks per CTA: 0-1 = A rows, 2-9 = B rows.
    for (int t = wid; t < 10; t += 4) {
        if (t < 2) prep_a_row(flat * 2 + t, lane, head, rel, rid);
        else       prep_b_row(flat * 8 + (t - 2), lane, tail);
    }
    __threadfence();

    // ---- Phase 2: grid barrier (monotonic generation counter; replay-safe).
    __syncthreads();
    if (tid == 0) {
        unsigned long long ticket = atomicAdd(&g_bar, 1ULL);
        unsigned long long target = ((ticket >> 8) + 1) << 8;
        unsigned long long cur;
        do {
            asm volatile("ld.acquire.gpu.global.u64 %0, [%1];"
                         : "=l"(cur) : "l"(&g_bar));
            if (cur >= target) break;
            __nanosleep(64);
        } while (true);
    }
    __syncthreads();

    // ---- Phase 3: GEMM (identical to R8)
    int wm = wid & 1;
    int wn = wid >> 1;
    int bn0 = blockIdx.x * BN;
    int bm0 = blockIdx.y * BM;
    int groupID = lane >> 2;
    int tig = lane & 3;

    float acc[2][4][4];
    #pragma unroll
    for (int mi = 0; mi < 2; mi++)
        #pragma unroll
        for (int ni = 0; ni < 4; ni++)
            #pragma unroll
            for (int q = 0; q < 4; q++) acc[mi][ni][q] = 0.f;

    uint32_t asw = s2u(&As[0][0]);
    uint32_t bsw = s2u(&Bs[0][0]);

    int aRow = (lane & 7) + ((lane >> 3) & 1) * 8;
    int aKh  = (lane >> 4) * 8;
    int bRowOff = ((lane >> 4) & 1) * 8 + (lane & 7);
    int bKh     = ((lane >> 3) & 1) * 8;

    auto issue = [&](int ic) {
        if (ic < NCH) {
            int stg = ic % STG;
            uint32_t aD = asw + stg * (BM * KC * 2);
            uint32_t bD = bsw + stg * (BN * KC * 2);
            int k0 = ic * KC;
            #pragma unroll
            for (int i = 0; i < 4; i++) {
                int idx = i * 128 + tid;
                int r = idx >> 3, c = idx & 7;
                cpasync16(aD + sw128(r * 128 + c * 16),
                          &g_Ah[(size_t)(bm0 + r) * KDIM + k0 + c * 8]);
                cpasync16(bD + sw128(r * 128 + c * 16),
                          &g_Bh[(size_t)(bn0 + r) * KDIM + k0 + c * 8]);
            }
        }
        asm volatile("cp.async.commit_group;" ::: "memory");
    };

    issue(0);
    issue(1);

    for (int it = 0; it < NCH; it++) {
        asm volatile("cp.async.wait_group 1;" ::: "memory");
        __syncthreads();
        issue(it + 2);

        int stg = it % STG;
        uint32_t aBase = asw + stg * (BM * KC * 2);
        uint32_t bBase = bsw + stg * (BN * KC * 2);

        #pragma unroll
        for (int kk = 0; kk < 4; kk++) {
            uint32_t af[2][4];
            #pragma unroll
            for (int mi = 0; mi < 2; mi++) {
                int row = wm * 32 + mi * 16 + aRow;
                int kcol = kk * 16 + aKh;
                uint32_t addr = aBase + sw128((uint32_t)(row * 128 + kcol * 2));
                asm volatile(
                    "ldmatrix.sync.aligned.m8n8.x4.shared.b16 {%0,%1,%2,%3}, [%4];"
                    : "=r"(af[mi][0]), "=r"(af[mi][1]), "=r"(af[mi][2]), "=r"(af[mi][3])
                    : "r"(addr));
            }
            uint32_t bf[4][2];
            #pragma unroll
            for (int p = 0; p < 2; p++) {
                int n = wn * 32 + p * 16 + bRowOff;
                int kcol = kk * 16 + bKh;
                uint32_t addr = bBase + sw128((uint32_t)(n * 128 + kcol * 2));
                asm volatile(
                    "ldmatrix.sync.aligned.m8n8.x4.shared.b16 {%0,%1,%2,%3}, [%4];"
                    : "=r"(bf[p * 2][0]), "=r"(bf[p * 2][1]),
                      "=r"(bf[p * 2 + 1][0]), "=r"(bf[p * 2 + 1][1])
                    : "r"(addr));
            }
            #pragma unroll
            for (int mi = 0; mi < 2; mi++)
                #pragma unroll
                for (int ni = 0; ni < 4; ni++) {
                    asm volatile(
                        "mma.sync.aligned.m16n8k16.row.col.f32.f16.f16.f32 "
                        "{%0,%1,%2,%3}, {%4,%5,%6,%7}, {%8,%9}, {%0,%1,%2,%3};"
                        : "+f"(acc[mi][ni][0]), "+f"(acc[mi][ni][1]),
                          "+f"(acc[mi][ni][2]), "+f"(acc[mi][ni][3])
                        : "r"(af[mi][0]), "r"(af[mi][1]), "r"(af[mi][2]), "r"(af[mi][3]),
                          "r"(bf[ni][0]), "r"(bf[ni][1]));
                }
        }
    }

    #pragma unroll
    for (int mi = 0; mi < 2; mi++) {
        int r0 = bm0 + wm * 32 + mi * 16 + groupID;
        int r1 = r0 + 8;
        float c0 = g_c[r0];
        float c1 = g_c[r1];
        #pragma unroll
        for (int ni = 0; ni < 4; ni++) {
            int col = bn0 + wn * 32 + ni * 8 + tig * 2;
            float2 v0, v1;
            v0.x = -sqrtf(fmaxf(acc[mi][ni][0] + c0, 0.f));
            v0.y = -sqrtf(fmaxf(acc[mi][ni][1] + c0, 0.f));
            v1.x = -sqrtf(fmaxf(acc[mi][ni][2] + c1, 0.f));
            v1.y = -sqrtf(fmaxf(acc[mi][ni][3] + c1, 0.f));
            *reinterpret_cast<float2*>(out + (size_t)r0 * NNEG + col) = v0;
            *reinterpret_cast<float2*>(out + (size_t)r1 * NNEG + col) = v1;
        }
    }
}

// ---------------------------------------------------------------------------
extern "C" void kernel_launch(void* const* d_in, const int* in_sizes, int n_in,
                              void* d_out, int out_size) {
    const float* head = (const float*)d_in[0];       // (512, 256)
    const float* tail = (const float*)d_in[1];       // (1, 2048, 256)
    const float* rel  = (const float*)d_in[2];       // (1000, 512)
    const int*   rid  = (const int*)d_in[3];         // (512,) int32
    float* out = (float*)d_out;                      // (512, 2048)

    dim3 grid(NNEG / BN, BATCH / BM);                // 32 x 8 = 256 CTAs
    fused_kernel<<<grid, 128>>>(out, head, tail, rel, rid);
}